// round 10
// baseline (speedup 1.0000x reference)
#include <cuda_runtime.h>
#include <cstdint>

#define T_STEPS 1000
#define BATCH   8192
#define IN      9
#define HID     96
#define OUTD    3
#define GRP     16
#define HS      6
#define HP      3
#define EPT     2                    // batch elements per thread
#define CH      5                    // timesteps per staged chunk
#define NC      (T_STEPS / CH)       // 200 chunks
#define BPBX    16                   // batches per block (8 groups x 2)
#define ROWP    10                   // padded u64 slots per (t, batch) row
#define CHF     (CH * BPBX * IN)     // valid elements per chunk = 720
#define NLD     6                    // ceil(720/128)

typedef unsigned long long u64;

union f2u {
    u64 u;
    float f[2];
};

__device__ __forceinline__ u64 pack2(float lo, float hi) {
    f2u v; v.f[0] = lo; v.f[1] = hi; return v.u;
}
__device__ __forceinline__ u64 ffma2(u64 a, u64 b, u64 c) {
    u64 d;
    asm("fma.rn.f32x2 %0, %1, %2, %3;" : "=l"(d) : "l"(a), "l"(b), "l"(c));
    return d;
}

__global__ __launch_bounds__(128, 4)
void snn_kernel(const float* __restrict__ X,
                const float* __restrict__ W1,
                const float* __restrict__ B1,
                const float* __restrict__ W2,
                const float* __restrict__ B2,
                float* __restrict__ out)
{
    __shared__ alignas(16) u64 xs[2][CH * BPBX * ROWP];  // x duplicated {f,f}

    const int tix  = threadIdx.x;
    const int pos  = tix & 15;                 // lane within 16-thread group
    const int g    = tix >> 4;                 // group 0..7
    const int blA  = g * EPT;                  // local batch of element 0
    const int bA   = blockIdx.x * BPBX + blA;  // global batch of element 0
    const int hbase = pos * HS;
    const int ch   = pos & 3;                  // output channel (3 = idle lane)
    const int chc  = (ch < 3) ? ch : 2;

    // ---- Weight slices to registers (shared by both elements): 78 regs ----
    u64 w1p[IN][HP];
#pragma unroll
    for (int j = 0; j < HP; j++) {
        const int h0 = hbase + 2 * j;
#pragma unroll
        for (int i = 0; i < IN; i++)
            w1p[i][j] = pack2(W1[h0 * IN + i], W1[(h0 + 1) * IN + i]);
    }
    u64 b1p[HP];
#pragma unroll
    for (int j = 0; j < HP; j++)
        b1p[j] = pack2(B1[hbase + 2 * j], B1[hbase + 2 * j + 1]);

    u64 w2p[OUTD][HP];
#pragma unroll
    for (int o = 0; o < OUTD; o++)
#pragma unroll
        for (int j = 0; j < HP; j++)
            w2p[o][j] = pack2(W2[o * HID + hbase + 2 * j],
                              W2[o * HID + hbase + 2 * j + 1]);

    const float bk = B2[chc];

    const u64 BETA2 = 0x3F6B851F3F6B851Full;   // {0.92, 0.92}
    u64 NEGINVB2;
    { f2u v; v.f[0] = -(1.0f / 0.92f); v.f[1] = v.f[0]; NEGINVB2 = v.u; }

    // ---- State (m-tilde fold), two batch elements ----
    u64 mt[EPT][HP];
#pragma unroll
    for (int e = 0; e < EPT; e++)
#pragma unroll
        for (int j = 0; j < HP; j++) mt[e][j] = 0ull;
    float mloc[EPT], sloc[EPT];
#pragma unroll
    for (int e = 0; e < EPT; e++) { mloc[e] = 0.f; sloc[e] = 0.f; }

    const int orow    = BATCH * OUTD;
    const int memoff  = T_STEPS * orow;
    const int cstride = CH * BATCH * IN;

    // writer lanes: pos 0-2 -> spk2[ch], pos 4-6 -> mem2[ch]
    const bool writer = (ch < 3) && (pos < 8);
    const bool is_spk = (pos < 4);
    float* stp = out + bA * OUTD + chc + (is_spk ? 0 : memoff);

    // ---- Prologue: stage chunk 0 (offsets recomputed, not cached) ----
    float stage[NLD];
#pragma unroll
    for (int k = 0; k < NLD; k++) {
        const int j = tix + 128 * k;
        if (j < CHF) {
            const int tl  = j / (BPBX * IN);
            const int rem = j - tl * (BPBX * IN);
            stage[k] = __ldg(X + tl * (BATCH * IN) + blockIdx.x * (BPBX * IN) + rem);
        }
    }
#pragma unroll
    for (int k = 0; k < NLD; k++) {
        const int j = tix + 128 * k;
        if (j < CHF) {
            const int tl  = j / (BPBX * IN);
            const int rem = j - tl * (BPBX * IN);
            const int bll = rem / IN;
            const int ii  = rem - bll * IN;
            xs[0][(tl * BPBX + bll) * ROWP + ii] = pack2(stage[k], stage[k]);
        }
    }
    __syncthreads();

#pragma unroll 1
    for (int c = 0; c < NC; c++) {
        const bool more = (c + 1 < NC);
        if (more) {
            const float* xb = X + (c + 1) * cstride;
#pragma unroll
            for (int k = 0; k < NLD; k++) {
                const int j = tix + 128 * k;
                if (j < CHF) {
                    const int tl  = j / (BPBX * IN);
                    const int rem = j - tl * (BPBX * IN);
                    stage[k] = __ldg(xb + tl * (BATCH * IN)
                                     + blockIdx.x * (BPBX * IN) + rem);
                }
            }
        }

        const u64* xbase = &xs[c & 1][blA * ROWP];

#pragma unroll 1
        for (int s = 0; s < CH; s++) {
            float v[EPT];

#pragma unroll
            for (int e = 0; e < EPT; e++) {
                const u64* xrow = xbase + s * (BPBX * ROWP) + e * ROWP;

                // layer 1: m = beta*m~ + b1 + x@W1slice
                u64 mp[HP];
#pragma unroll
                for (int j = 0; j < HP; j++)
                    mp[j] = ffma2(BETA2, mt[e][j], b1p[j]);
#pragma unroll
                for (int i = 0; i < IN; i++) {
                    const u64 xd = xrow[i];
#pragma unroll
                    for (int j = 0; j < HP; j++)
                        mp[j] = ffma2(xd, w1p[i][j], mp[j]);
                }

                // spike + reset fold + layer-2 partials
                u64 c0 = 0ull, c1 = 0ull, c2 = 0ull;
#pragma unroll
                for (int j = 0; j < HP; j++) {
                    f2u m; m.u = mp[j];
                    f2u sv;
                    sv.f[0] = (m.f[0] > 1.0f) ? 1.0f : 0.0f;
                    sv.f[1] = (m.f[1] > 1.0f) ? 1.0f : 0.0f;
                    mt[e][j] = ffma2(sv.u, NEGINVB2, mp[j]);
                    c0 = ffma2(sv.u, w2p[0][j], c0);
                    c1 = ffma2(sv.u, w2p[1][j], c1);
                    c2 = ffma2(sv.u, w2p[2][j], c2);
                }
                f2u a0, a1, a2;
                a0.u = c0; a1.u = c1; a2.u = c2;
                float r0 = a0.f[0] + a0.f[1];
                float r1 = a1.f[0] + a1.f[1];
                float r2 = a2.f[0] + a2.f[1];

                // levels 1,2 on all channels, scatter, levels 4,8 on own
                r0 += __shfl_xor_sync(0xffffffffu, r0, 1);
                r1 += __shfl_xor_sync(0xffffffffu, r1, 1);
                r2 += __shfl_xor_sync(0xffffffffu, r2, 1);
                r0 += __shfl_xor_sync(0xffffffffu, r0, 2);
                r1 += __shfl_xor_sync(0xffffffffu, r1, 2);
                r2 += __shfl_xor_sync(0xffffffffu, r2, 2);
                float t = r0;
                t = (ch == 1) ? r1 : t;
                t = (ch == 2) ? r2 : t;
                t += __shfl_xor_sync(0xffffffffu, t, 4);
                t += __shfl_xor_sync(0xffffffffu, t, 8);
                v[e] = t;
            }

            // mem2 updates (independent chains) + stores
#pragma unroll
            for (int e = 0; e < EPT; e++) {
                mloc[e] = fmaf(0.92f, mloc[e], v[e] + bk) - sloc[e];
                sloc[e] = (mloc[e] > 1.0f) ? 1.0f : 0.0f;
            }
            if (writer) {
                stp[0]    = is_spk ? sloc[0] : mloc[0];
                stp[OUTD] = is_spk ? sloc[1] : mloc[1];   // batch bA+1
            }
            stp += orow;
        }

        if (more) {
#pragma unroll
            for (int k = 0; k < NLD; k++) {
                const int j = tix + 128 * k;
                if (j < CHF) {
                    const int tl  = j / (BPBX * IN);
                    const int rem = j - tl * (BPBX * IN);
                    const int bll = rem / IN;
                    const int ii  = rem - bll * IN;
                    xs[(c + 1) & 1][(tl * BPBX + bll) * ROWP + ii] =
                        pack2(stage[k], stage[k]);
                }
            }
            __syncthreads();
        }
    }
}

extern "C" void kernel_launch(void* const* d_in, const int* in_sizes, int n_in,
                              void* d_out, int out_size)
{
    const float* X  = (const float*)d_in[0];
    const float* W1 = (const float*)d_in[1];
    const float* B1 = (const float*)d_in[2];
    const float* W2 = (const float*)d_in[3];
    const float* B2 = (const float*)d_in[4];
    float* out = (float*)d_out;

    snn_kernel<<<BATCH / BPBX, 128>>>(X, W1, B1, W2, B2, out);  // 512 blocks
}